// round 2
// baseline (speedup 1.0000x reference)
#include <cuda_runtime.h>
#include <math.h>

#define TT 512
#define BB 64
#define EE 300
#define HH 512
#define LL 5
#define TB (TT*BB)
#define G3 (3*HH)

// ---------------- scratch (static device globals; no allocation) ----------------
__device__ float g_x[TB * EE];     // embedded inputs [T*B, 300]
__device__ float g_xp[TB * G3];    // input projections for current layer [T*B, 1536]
__device__ float g_h1[TB * HH];    // layer-0 hidden outputs [T*B, 512]
__device__ float g_h2[TB * HH];    // layer-1 hidden outputs [T*B, 512]
__device__ int   g_bar[2][TT * 4]; // per (layer, step, batch-group) barrier counters

// ---------------- barrier reset (runs before each full pipeline) ----------------
__global__ void zero_bar_kernel() {
    int i = blockIdx.x * blockDim.x + threadIdx.x;
    if (i < 2 * TT * 4) ((int*)g_bar)[i] = 0;
}

// ---------------- embedding gather ----------------
__global__ void embed_kernel(const int* __restrict__ texts,
                             const float* __restrict__ emb) {
    int row = blockIdx.x;                       // t*B + b
    int v = texts[row];
    const float* src = emb + (size_t)v * EE;
    float* dst = g_x + (size_t)row * EE;
    for (int e = threadIdx.x; e < EE; e += blockDim.x) dst[e] = src[e];
}

// ---------------- C[M,1536] = A[M,K] @ W[1536,K]^T + bias ----------------
// BM=128, BN=64, BK=8, 256 threads, 8x4 per-thread tile.
__global__ void gemm_bias_kernel(const float* __restrict__ W,
                                 const float* __restrict__ bias,
                                 int K, int useA1) {
    __shared__ float As[8][132];
    __shared__ float Bs[8][68];
    const float* A = useA1 ? g_h1 : g_x;
    float* C = g_xp;
    const int tid = threadIdx.x;
    const int bm = blockIdx.x * 128;
    const int bn = blockIdx.y * 64;
    const int ty = tid >> 4, tx = tid & 15;
    float acc[8][4];
#pragma unroll
    for (int i = 0; i < 8; i++)
#pragma unroll
        for (int j = 0; j < 4; j++) acc[i][j] = 0.f;

    for (int k0 = 0; k0 < K; k0 += 8) {
        // load A tile (128 x 8), k-major in smem
        {
            int i = tid * 4;
            int m = i >> 3, kk = i & 7;
            const float* ap = A + (size_t)(bm + m) * K + (k0 + kk);
            if (k0 + kk + 3 < K) {
                float4 v = *(const float4*)ap;
                As[kk + 0][m] = v.x; As[kk + 1][m] = v.y;
                As[kk + 2][m] = v.z; As[kk + 3][m] = v.w;
            } else {
#pragma unroll
                for (int q = 0; q < 4; q++) {
                    int k = k0 + kk + q;
                    As[kk + q][m] = (k < K) ? A[(size_t)(bm + m) * K + k] : 0.f;
                }
            }
        }
        // load B tile (64 x 8)
        if (tid < 128) {
            int i = tid * 4;
            int n = i >> 3, kk = i & 7;
            const float* wp = W + (size_t)(bn + n) * K + (k0 + kk);
            if (k0 + kk + 3 < K) {
                float4 v = *(const float4*)wp;
                Bs[kk + 0][n] = v.x; Bs[kk + 1][n] = v.y;
                Bs[kk + 2][n] = v.z; Bs[kk + 3][n] = v.w;
            } else {
#pragma unroll
                for (int q = 0; q < 4; q++) {
                    int k = k0 + kk + q;
                    Bs[kk + q][n] = (k < K) ? W[(size_t)(bn + n) * K + k] : 0.f;
                }
            }
        }
        __syncthreads();
#pragma unroll
        for (int kk = 0; kk < 8; kk++) {
            float a[8], b[4];
            *(float4*)&a[0] = *(const float4*)&As[kk][ty * 8];
            *(float4*)&a[4] = *(const float4*)&As[kk][ty * 8 + 4];
            *(float4*)&b[0] = *(const float4*)&Bs[kk][tx * 4];
#pragma unroll
            for (int i = 0; i < 8; i++)
#pragma unroll
                for (int j = 0; j < 4; j++) acc[i][j] = fmaf(a[i], b[j], acc[i][j]);
        }
        __syncthreads();
    }
    float4 bv = *(const float4*)&bias[bn + tx * 4];
#pragma unroll
    for (int i = 0; i < 8; i++) {
        float4 o;
        o.x = acc[i][0] + bv.x; o.y = acc[i][1] + bv.y;
        o.z = acc[i][2] + bv.z; o.w = acc[i][3] + bv.w;
        *(float4*)&C[(size_t)(bm + ty * 8 + i) * G3 + bn + tx * 4] = o;
    }
}

// ---------------- persistent GRU recurrence ----------------
// Grid = 128 CTAs = 4 batch-slices (16 batches) x 32 hidden-slices (16 cols).
// Weight slice (48 rows x 512) stays in SMEM for all 512 steps.
// Each thread owns one (b, j): computes r/z/n dots + nonlinearity locally.
__device__ __forceinline__ float sigmoidf_(float x) { return 1.f / (1.f + __expf(-x)); }

#define WPAD 516  // stride: /4 odd -> conflict-free LDS.128; multiple of 4 -> aligned

__global__ void gru_kernel(const float* __restrict__ Whh,
                           const float* __restrict__ bhh,
                           int layer) {
    extern __shared__ float sm[];
    float* Wsm = sm;                 // 48 * 516
    float* hsm = sm + 48 * WPAD;     // 16 * 516
    __shared__ float bsm[48];
    const float* xp = g_xp;
    float* hout = layer ? g_h2 : g_h1;
    int* bar = g_bar[layer];

    const int tid = threadIdx.x;
    const int bs = blockIdx.x & 3;
    const int js = blockIdx.x >> 2;
    const int b0 = bs * 16, j0 = js * 16;

    // load weight slice: rows {j0..j0+15} of each gate (r, z, n)
    for (int idx = tid; idx < 48 * 512; idx += 256) {
        int r = idx >> 9, k = idx & 511;
        int g = r >> 4, j = r & 15;
        Wsm[r * WPAD + k] = Whh[(size_t)(g * 512 + j0 + j) * 512 + k];
    }
    if (tid < 48) {
        int g = tid >> 4, j = tid & 15;
        bsm[tid] = bhh[g * 512 + j0 + j];
    }
    for (int idx = tid; idx < 16 * WPAD; idx += 256) hsm[idx] = 0.f;  // h0 = 0
    __syncthreads();

    const int b = tid >> 4, j = tid & 15;
    const float* wr = Wsm + j * WPAD;
    const float* wz = Wsm + (16 + j) * WPAD;
    const float* wn = Wsm + (32 + j) * WPAD;
    const float* hrow = hsm + b * WPAD;
    const float br = bsm[j], bz = bsm[16 + j], bn_ = bsm[32 + j];

    for (int t = 0; t < TT; t++) {
        float ar = 0.f, az = 0.f, an = 0.f;
#pragma unroll 4
        for (int k = 0; k < 512; k += 4) {
            float4 hv = *(const float4*)(hrow + k);
            float4 v1 = *(const float4*)(wr + k);
            float4 v2 = *(const float4*)(wz + k);
            float4 v3 = *(const float4*)(wn + k);
            ar = fmaf(hv.x, v1.x, ar); ar = fmaf(hv.y, v1.y, ar);
            ar = fmaf(hv.z, v1.z, ar); ar = fmaf(hv.w, v1.w, ar);
            az = fmaf(hv.x, v2.x, az); az = fmaf(hv.y, v2.y, az);
            az = fmaf(hv.z, v2.z, az); az = fmaf(hv.w, v2.w, az);
            an = fmaf(hv.x, v3.x, an); an = fmaf(hv.y, v3.y, an);
            an = fmaf(hv.z, v3.z, an); an = fmaf(hv.w, v3.w, an);
        }
        const float* xpt = xp + ((size_t)t * BB + b0 + b) * G3 + j0 + j;
        float xr = xpt[0], xz = xpt[512], xn = xpt[1024];
        float r = sigmoidf_(xr + ar + br);
        float z = sigmoidf_(xz + az + bz);
        float n = tanhf(xn + r * (an + bn_));
        float hprev = hrow[j0 + j];
        float hnew = (1.f - z) * n + z * hprev;
        hout[((size_t)t * BB + b0 + b) * HH + j0 + j] = hnew;

        if (t == TT - 1) break;

        // group barrier across the 32 hidden-slice CTAs sharing this batch-slice
        __threadfence();
        __syncthreads();
        if (tid == 0) {
            atomicAdd(&bar[t * 4 + bs], 1);
            volatile int* p = &bar[t * 4 + bs];
            while (*p < 32) { }
            __threadfence();
        }
        __syncthreads();

        // reload full h[t] for our 16 batches (written across 32 peer CTAs)
        for (int idx = tid; idx < 16 * 128; idx += 256) {
            int bb = idx >> 7, k4 = (idx & 127) * 4;
            *(float4*)(hsm + bb * WPAD + k4) =
                *(const float4*)(hout + ((size_t)t * BB + b0 + bb) * HH + k4);
        }
        __syncthreads();
    }
}

// ---------------- mean pool over batch + FC ----------------
__global__ void pool_fc_kernel(const float* __restrict__ fcW,
                               const float* __restrict__ fcb,
                               float* __restrict__ out) {
    __shared__ float pooled[HH];
    int t = blockIdx.x;
    const float* base = g_h2 + (size_t)t * BB * HH;
    for (int h = threadIdx.x; h < HH; h += blockDim.x) {
        float s = 0.f;
        for (int b = 0; b < BB; b++) s += base[b * HH + h];
        pooled[h] = s * (1.f / 64.f);
    }
    __syncthreads();
    int w = threadIdx.x >> 5, lane = threadIdx.x & 31;
    if (w < LL) {
        float s = 0.f;
        for (int h = lane; h < HH; h += 32) s = fmaf(pooled[h], fcW[w * HH + h], s);
#pragma unroll
        for (int o = 16; o > 0; o >>= 1) s += __shfl_xor_sync(0xffffffffu, s, o);
        if (lane == 0) out[t * LL + w] = s + fcb[w];
    }
}

// ---------------- launch ----------------
extern "C" void kernel_launch(void* const* d_in, const int* in_sizes, int n_in,
                              void* d_out, int out_size) {
    (void)in_sizes; (void)n_in; (void)out_size;
    const int*   texts = (const int*)d_in[0];
    const float* emb   = (const float*)d_in[1];
    const float* Wih0  = (const float*)d_in[2];
    const float* Whh0  = (const float*)d_in[3];
    const float* bih0  = (const float*)d_in[4];
    const float* bhh0  = (const float*)d_in[5];
    const float* Wih1  = (const float*)d_in[6];
    const float* Whh1  = (const float*)d_in[7];
    const float* bih1  = (const float*)d_in[8];
    const float* bhh1  = (const float*)d_in[9];
    const float* fcW   = (const float*)d_in[10];
    const float* fcb   = (const float*)d_in[11];
    float* out = (float*)d_out;

    const int gru_smem = 64 * WPAD * 4;  // 132096 B dynamic smem
    cudaFuncSetAttribute(gru_kernel, cudaFuncAttributeMaxDynamicSharedMemorySize,
                         gru_smem);

    zero_bar_kernel<<<16, 256>>>();
    embed_kernel<<<TB, 128>>>(texts, emb);

    dim3 ggrid(TB / 128, G3 / 64);
    gemm_bias_kernel<<<ggrid, 256>>>(Wih0, bih0, EE, 0);          // xp0 from g_x
    gru_kernel<<<128, 256, gru_smem>>>(Whh0, bhh0, 0);            // -> g_h1
    gemm_bias_kernel<<<ggrid, 256>>>(Wih1, bih1, HH, 1);          // xp1 from g_h1
    gru_kernel<<<128, 256, gru_smem>>>(Whh1, bhh1, 1);            // -> g_h2
    pool_fc_kernel<<<TT, 256>>>(fcW, fcb, out);
}

// round 3
// speedup vs baseline: 2.1827x; 2.1827x over previous
#include <cuda_runtime.h>
#include <math.h>
#include <stdint.h>

#define TT 512
#define BB 64
#define EE 300
#define HH 512
#define LL 5
#define TB (TT*BB)
#define G3 (3*HH)

// ---------------- scratch (static device globals; no allocation) ----------------
__device__ float g_x[TB * EE];     // embedded inputs [T*B, 300]
__device__ float g_xp[TB * G3];    // input projections for current layer [T*B, 1536]
__device__ float g_h1[TB * HH];    // layer-0 hidden outputs [T*B, 512]
__device__ float g_h2[TB * HH];    // layer-1 hidden outputs [T*B, 512]
__device__ int   g_bar[2][TT * 4]; // per (layer, step, batch-group) barrier counters

// ---------------- barrier reset ----------------
__global__ void zero_bar_kernel() {
    int i = blockIdx.x * blockDim.x + threadIdx.x;
    if (i < 2 * TT * 4) ((int*)g_bar)[i] = 0;
}

// ---------------- embedding gather ----------------
__global__ void embed_kernel(const int* __restrict__ texts,
                             const float* __restrict__ emb) {
    int row = blockIdx.x;                       // t*B + b
    int v = texts[row];
    const float* src = emb + (size_t)v * EE;
    float* dst = g_x + (size_t)row * EE;
    for (int e = threadIdx.x; e < EE; e += blockDim.x) dst[e] = src[e];
}

// ---------------- C[M,1536] = A[M,K] @ W[1536,K]^T + bias (fp32 SIMT) ----------------
__global__ void gemm_bias_kernel(const float* __restrict__ W,
                                 const float* __restrict__ bias,
                                 int K, int useA1) {
    __shared__ float As[8][132];
    __shared__ float Bs[8][68];
    const float* A = useA1 ? g_h1 : g_x;
    float* C = g_xp;
    const int tid = threadIdx.x;
    const int bm = blockIdx.x * 128;
    const int bn = blockIdx.y * 64;
    const int ty = tid >> 4, tx = tid & 15;
    float acc[8][4];
#pragma unroll
    for (int i = 0; i < 8; i++)
#pragma unroll
        for (int j = 0; j < 4; j++) acc[i][j] = 0.f;

    for (int k0 = 0; k0 < K; k0 += 8) {
        {
            int i = tid * 4;
            int m = i >> 3, kk = i & 7;
            const float* ap = A + (size_t)(bm + m) * K + (k0 + kk);
            if (k0 + kk + 3 < K) {
                float4 v = *(const float4*)ap;
                As[kk + 0][m] = v.x; As[kk + 1][m] = v.y;
                As[kk + 2][m] = v.z; As[kk + 3][m] = v.w;
            } else {
#pragma unroll
                for (int q = 0; q < 4; q++) {
                    int k = k0 + kk + q;
                    As[kk + q][m] = (k < K) ? A[(size_t)(bm + m) * K + k] : 0.f;
                }
            }
        }
        if (tid < 128) {
            int i = tid * 4;
            int n = i >> 3, kk = i & 7;
            const float* wp = W + (size_t)(bn + n) * K + (k0 + kk);
            if (k0 + kk + 3 < K) {
                float4 v = *(const float4*)wp;
                Bs[kk + 0][n] = v.x; Bs[kk + 1][n] = v.y;
                Bs[kk + 2][n] = v.z; Bs[kk + 3][n] = v.w;
            } else {
#pragma unroll
                for (int q = 0; q < 4; q++) {
                    int k = k0 + kk + q;
                    Bs[kk + q][n] = (k < K) ? W[(size_t)(bn + n) * K + k] : 0.f;
                }
            }
        }
        __syncthreads();
#pragma unroll
        for (int kk = 0; kk < 8; kk++) {
            float a[8], b[4];
            *(float4*)&a[0] = *(const float4*)&As[kk][ty * 8];
            *(float4*)&a[4] = *(const float4*)&As[kk][ty * 8 + 4];
            *(float4*)&b[0] = *(const float4*)&Bs[kk][tx * 4];
#pragma unroll
            for (int i = 0; i < 8; i++)
#pragma unroll
                for (int j = 0; j < 4; j++) acc[i][j] = fmaf(a[i], b[j], acc[i][j]);
        }
        __syncthreads();
    }
    float4 bv = *(const float4*)&bias[bn + tx * 4];
#pragma unroll
    for (int i = 0; i < 8; i++) {
        float4 o;
        o.x = acc[i][0] + bv.x; o.y = acc[i][1] + bv.y;
        o.z = acc[i][2] + bv.z; o.w = acc[i][3] + bv.w;
        *(float4*)&C[(size_t)(bm + ty * 8 + i) * G3 + bn + tx * 4] = o;
    }
}

// ---------------- persistent GRU recurrence (tf32 mma.sync) ----------------
// Grid = 128 CTAs = 4 batch-groups (16 b) x 32 hidden-slices (16 j -> 48 gate cols).
// Warps 0-5 each own one 8-col n-tile, holding B-fragments (W) in 128 registers
// for all 512 steps. A-fragments (h) read from SMEM each step (conflict-free).
// Accumulators persist in C fragments across K. hprev kept exactly in registers.
__device__ __forceinline__ float sigmoidf_(float x) { return 1.f / (1.f + __expf(-x)); }

__device__ __forceinline__ uint32_t cvt_tf32(float f) {
    uint32_t u;
    asm("cvt.rna.tf32.f32 %0, %1;" : "=r"(u) : "f"(f));
    return u;
}

#define HP 516  // hsm row stride: (516 % 32) == 4 -> A-frag banks (4r+c)%32 conflict-free

__global__ void __launch_bounds__(256, 1)
gru_kernel(const float* __restrict__ Whh,
           const float* __restrict__ bhh,
           int layer) {
    __shared__ float hsm[16 * HP];   // h[t] for our 16 batches (tf32-rounded)
    __shared__ float gsm[16 * 48];   // recurrent gate pre-activations
    __shared__ float bsm[48];

    const float* xp = g_xp;
    float* hout = layer ? g_h2 : g_h1;
    int* bar = g_bar[layer];

    const int tid = threadIdx.x;
    const int warp = tid >> 5;
    const int lane = tid & 31;
    const int bs = blockIdx.x & 3;
    const int js = blockIdx.x >> 2;
    const int b0 = bs * 16, j0 = js * 16;

    if (tid < 48) {
        int g = tid >> 4, j = tid & 15;
        bsm[tid] = bhh[g * 512 + j0 + j];
    }

    // ---- load W B-fragments into registers (warps 0-5 only) ----
    uint32_t wb0[64], wb1[64];
    const int r = lane >> 2, c = lane & 3;
    if (warp < 6) {
        int cg = warp * 8 + r;           // gate-col 0..47
        int g = cg >> 4, jj = cg & 15;
        const float* wrow = Whh + (size_t)(g * 512 + j0 + jj) * 512;
#pragma unroll
        for (int ks = 0; ks < 64; ks++) {
            wb0[ks] = cvt_tf32(wrow[ks * 8 + c]);
            wb1[ks] = cvt_tf32(wrow[ks * 8 + c + 4]);
        }
    }

    for (int idx = tid; idx < 16 * HP; idx += 256) hsm[idx] = 0.f;  // h0 = 0
    __syncthreads();

    // static (b, j) ownership for the gate phase: one pair per thread
    const int gb = tid >> 4, gj = tid & 15;
    const float br = bsm[gj], bz = bsm[16 + gj], bn_ = bsm[32 + gj];
    float hprev = 0.f;

    const float* arow0 = hsm + r * HP;        // batch r
    const float* arow1 = hsm + (r + 8) * HP;  // batch r + 8

    for (int t = 0; t < TT; t++) {
        // prefetch xp for this thread's (b, j) early: hidden behind the mma loop
        const float* xpt = xp + ((size_t)t * BB + b0 + gb) * G3 + j0 + gj;
        float xr = xpt[0], xz = xpt[512], xn = xpt[1024];

        if (warp < 6) {
            float acc0 = 0.f, acc1 = 0.f, acc2 = 0.f, acc3 = 0.f;
#pragma unroll
            for (int ks = 0; ks < 64; ks++) {
                int k = ks * 8;
                uint32_t a0 = __float_as_uint(arow0[k + c]);
                uint32_t a1 = __float_as_uint(arow1[k + c]);
                uint32_t a2 = __float_as_uint(arow0[k + c + 4]);
                uint32_t a3 = __float_as_uint(arow1[k + c + 4]);
                asm volatile(
                    "mma.sync.aligned.m16n8k8.row.col.f32.tf32.tf32.f32 "
                    "{%0,%1,%2,%3}, {%4,%5,%6,%7}, {%8,%9}, {%0,%1,%2,%3};\n"
                    : "+f"(acc0), "+f"(acc1), "+f"(acc2), "+f"(acc3)
                    : "r"(a0), "r"(a1), "r"(a2), "r"(a3),
                      "r"(wb0[ks]), "r"(wb1[ks]));
            }
            // C frag: (r, nw+2c), (r, nw+2c+1), (r+8, ...), (r+8, ...+1)
            int cc = warp * 8 + 2 * c;
            gsm[r * 48 + cc]           = acc0;
            gsm[r * 48 + cc + 1]       = acc1;
            gsm[(r + 8) * 48 + cc]     = acc2;
            gsm[(r + 8) * 48 + cc + 1] = acc3;
        }
        __syncthreads();

        // gate nonlinearity: thread owns (gb, gj)
        {
            float ar = gsm[gb * 48 + gj];
            float az = gsm[gb * 48 + 16 + gj];
            float an = gsm[gb * 48 + 32 + gj];
            float rr = sigmoidf_(xr + ar + br);
            float zz = sigmoidf_(xz + az + bz);
            float nn = tanhf(xn + rr * (an + bn_));
            float hnew = (1.f - zz) * nn + zz * hprev;
            hprev = hnew;
            hout[((size_t)t * BB + b0 + gb) * HH + j0 + gj] = hnew;
        }

        if (t == TT - 1) break;

        // group barrier across the 32 hidden-slice CTAs sharing this batch-group
        __threadfence();
        __syncthreads();
        if (tid == 0) {
            atomicAdd(&bar[t * 4 + bs], 1);
            volatile int* p = &bar[t * 4 + bs];
            while (*p < 32) { }
            __threadfence();
        }
        __syncthreads();

        // reload full h[t] for our 16 batches (tf32-round once here)
        for (int idx = tid; idx < 16 * 128; idx += 256) {
            int bb = idx >> 7, k4 = (idx & 127) * 4;
            float4 v = *(const float4*)(hout + ((size_t)t * BB + b0 + bb) * HH + k4);
            v.x = __uint_as_float(cvt_tf32(v.x));
            v.y = __uint_as_float(cvt_tf32(v.y));
            v.z = __uint_as_float(cvt_tf32(v.z));
            v.w = __uint_as_float(cvt_tf32(v.w));
            *(float4*)(hsm + bb * HP + k4) = v;
        }
        __syncthreads();
    }
}

// ---------------- mean pool over batch + FC ----------------
__global__ void pool_fc_kernel(const float* __restrict__ fcW,
                               const float* __restrict__ fcb,
                               float* __restrict__ out) {
    __shared__ float pooled[HH];
    int t = blockIdx.x;
    const float* base = g_h2 + (size_t)t * BB * HH;
    for (int h = threadIdx.x; h < HH; h += blockDim.x) {
        float s = 0.f;
        for (int b = 0; b < BB; b++) s += base[b * HH + h];
        pooled[h] = s * (1.f / 64.f);
    }
    __syncthreads();
    int w = threadIdx.x >> 5, lane = threadIdx.x & 31;
    if (w < LL) {
        float s = 0.f;
        for (int h = lane; h < HH; h += 32) s = fmaf(pooled[h], fcW[w * HH + h], s);
#pragma unroll
        for (int o = 16; o > 0; o >>= 1) s += __shfl_xor_sync(0xffffffffu, s, o);
        if (lane == 0) out[t * LL + w] = s + fcb[w];
    }
}

// ---------------- launch ----------------
extern "C" void kernel_launch(void* const* d_in, const int* in_sizes, int n_in,
                              void* d_out, int out_size) {
    (void)in_sizes; (void)n_in; (void)out_size;
    const int*   texts = (const int*)d_in[0];
    const float* emb   = (const float*)d_in[1];
    const float* Wih0  = (const float*)d_in[2];
    const float* Whh0  = (const float*)d_in[3];
    const float* bih0  = (const float*)d_in[4];
    const float* bhh0  = (const float*)d_in[5];
    const float* Wih1  = (const float*)d_in[6];
    const float* Whh1  = (const float*)d_in[7];
    const float* bih1  = (const float*)d_in[8];
    const float* bhh1  = (const float*)d_in[9];
    const float* fcW   = (const float*)d_in[10];
    const float* fcb   = (const float*)d_in[11];
    float* out = (float*)d_out;

    zero_bar_kernel<<<16, 256>>>();
    embed_kernel<<<TB, 128>>>(texts, emb);

    dim3 ggrid(TB / 128, G3 / 64);
    gemm_bias_kernel<<<ggrid, 256>>>(Wih0, bih0, EE, 0);   // xp0 from g_x
    gru_kernel<<<128, 256>>>(Whh0, bhh0, 0);               // -> g_h1
    gemm_bias_kernel<<<ggrid, 256>>>(Wih1, bih1, HH, 1);   // xp1 from g_h1
    gru_kernel<<<128, 256>>>(Whh1, bhh1, 1);               // -> g_h2
    pool_fc_kernel<<<TT, 256>>>(fcW, fcb, out);
}

// round 5
// speedup vs baseline: 2.6331x; 1.2064x over previous
#include <cuda_runtime.h>
#include <math.h>
#include <stdint.h>

#define TT 512
#define BB 64
#define EE 300
#define HH 512
#define LL 5
#define TB (TT*BB)
#define G3 (3*HH)

// ---------------- scratch (static device globals; no allocation) ----------------
__device__ float g_x[TB * EE];     // embedded inputs [T*B, 300]
__device__ float g_xp[TB * G3];    // input projections for current layer [T*B, 1536]
__device__ float g_h1[TB * HH];    // layer-0 hidden outputs [T*B, 512]
__device__ float g_h2[TB * HH];    // layer-1 hidden outputs [T*B, 512]
__device__ int   g_bar[2][TT * 4]; // per (layer, step, batch-group) barrier counters

__device__ __forceinline__ uint32_t cvt_tf32(float f) {
    uint32_t u;
    asm("cvt.rna.tf32.f32 %0, %1;" : "=r"(u) : "f"(f));
    return u;
}

// ---------------- barrier reset ----------------
__global__ void zero_bar_kernel() {
    int i = blockIdx.x * blockDim.x + threadIdx.x;
    if (i < 2 * TT * 4) ((int*)g_bar)[i] = 0;
}

// ---------------- embedding gather ----------------
__global__ void embed_kernel(const int* __restrict__ texts,
                             const float* __restrict__ emb) {
    int row = blockIdx.x;                       // t*B + b
    int v = texts[row];
    const float* src = emb + (size_t)v * EE;
    float* dst = g_x + (size_t)row * EE;
    for (int e = threadIdx.x; e < EE; e += blockDim.x) dst[e] = src[e];
}

// ---------------- C[M,1536] = A[M,K] @ W[1536,K]^T + bias  (tf32 mma) ----------------
// BM=128, BN=128, BK=16, 256 threads, 8 warps as 4(M) x 2(N), warp tile 32x64.
__global__ void __launch_bounds__(256)
gemm_tf32_kernel(const float* __restrict__ W,
                 const float* __restrict__ bias,
                 int K, int useA1) {
    __shared__ float As[16][136];   // [k][m], stride 136 -> conflict-free frag loads
    __shared__ float Bs[16][136];   // [k][n]
    const float* A = useA1 ? g_h1 : g_x;
    float* C = g_xp;
    const int tid = threadIdx.x;
    const int bm = blockIdx.x * 128;
    const int bn = blockIdx.y * 128;
    const int warp = tid >> 5, lane = tid & 31;
    const int wm = warp >> 1, wn = warp & 1;
    const int m0 = wm * 32, n0 = wn * 64;
    const int r = lane >> 2, c = lane & 3;

    float acc[2][8][4];
#pragma unroll
    for (int mt = 0; mt < 2; mt++)
#pragma unroll
        for (int nt = 0; nt < 8; nt++)
#pragma unroll
            for (int q = 0; q < 4; q++) acc[mt][nt][q] = 0.f;

    // loaders: threads 0-127 handle k 0..7, threads 128-255 handle k 8..15
    const int lrow = tid & 127;
    const int lk = (tid >> 7) * 8;

    for (int k0 = 0; k0 < K; k0 += 16) {
        {   // A tile: row (bm+lrow), k0+lk .. +7
            const float* ap = A + (size_t)(bm + lrow) * K + k0 + lk;
            float v[8];
            if (k0 + lk + 7 < K) {
                float4 p = *(const float4*)ap;
                float4 q4 = *(const float4*)(ap + 4);
                v[0]=p.x; v[1]=p.y; v[2]=p.z; v[3]=p.w;
                v[4]=q4.x; v[5]=q4.y; v[6]=q4.z; v[7]=q4.w;
            } else {
#pragma unroll
                for (int q = 0; q < 8; q++) {
                    int k = k0 + lk + q;
                    v[q] = (k < K) ? ap[q] : 0.f;
                }
            }
#pragma unroll
            for (int q = 0; q < 8; q++)
                As[lk + q][lrow] = __uint_as_float(cvt_tf32(v[q]));
        }
        {   // B tile: W row (bn+lrow), k0+lk .. +7
            const float* wp = W + (size_t)(bn + lrow) * K + k0 + lk;
            float v[8];
            if (k0 + lk + 7 < K) {
                float4 p = *(const float4*)wp;
                float4 q4 = *(const float4*)(wp + 4);
                v[0]=p.x; v[1]=p.y; v[2]=p.z; v[3]=p.w;
                v[4]=q4.x; v[5]=q4.y; v[6]=q4.z; v[7]=q4.w;
            } else {
#pragma unroll
                for (int q = 0; q < 8; q++) {
                    int k = k0 + lk + q;
                    v[q] = (k < K) ? wp[q] : 0.f;
                }
            }
#pragma unroll
            for (int q = 0; q < 8; q++)
                Bs[lk + q][lrow] = __uint_as_float(cvt_tf32(v[q]));
        }
        __syncthreads();
#pragma unroll
        for (int ks = 0; ks < 16; ks += 8) {
            uint32_t af[2][4], bf[8][2];
#pragma unroll
            for (int mt = 0; mt < 2; mt++) {
                int mm = m0 + mt * 16;
                af[mt][0] = __float_as_uint(As[ks + c][mm + r]);
                af[mt][1] = __float_as_uint(As[ks + c][mm + r + 8]);
                af[mt][2] = __float_as_uint(As[ks + c + 4][mm + r]);
                af[mt][3] = __float_as_uint(As[ks + c + 4][mm + r + 8]);
            }
#pragma unroll
            for (int nt = 0; nt < 8; nt++) {
                int nn = n0 + nt * 8 + r;
                bf[nt][0] = __float_as_uint(Bs[ks + c][nn]);
                bf[nt][1] = __float_as_uint(Bs[ks + c + 4][nn]);
            }
#pragma unroll
            for (int mt = 0; mt < 2; mt++)
#pragma unroll
                for (int nt = 0; nt < 8; nt++) {
                    asm volatile(
                        "mma.sync.aligned.m16n8k8.row.col.f32.tf32.tf32.f32 "
                        "{%0,%1,%2,%3}, {%4,%5,%6,%7}, {%8,%9}, {%0,%1,%2,%3};\n"
                        : "+f"(acc[mt][nt][0]), "+f"(acc[mt][nt][1]),
                          "+f"(acc[mt][nt][2]), "+f"(acc[mt][nt][3])
                        : "r"(af[mt][0]), "r"(af[mt][1]), "r"(af[mt][2]), "r"(af[mt][3]),
                          "r"(bf[nt][0]), "r"(bf[nt][1]));
                }
        }
        __syncthreads();
    }
    // epilogue: C frag (r, 2c), (r, 2c+1), (r+8, 2c), (r+8, 2c+1)
#pragma unroll
    for (int mt = 0; mt < 2; mt++) {
        int mrow = bm + m0 + mt * 16 + r;
#pragma unroll
        for (int nt = 0; nt < 8; nt++) {
            int col = bn + n0 + nt * 8 + 2 * c;
            float b0 = bias[col], b1 = bias[col + 1];
            float2 o0, o1;
            o0.x = acc[mt][nt][0] + b0; o0.y = acc[mt][nt][1] + b1;
            o1.x = acc[mt][nt][2] + b0; o1.y = acc[mt][nt][3] + b1;
            *(float2*)&C[(size_t)mrow * G3 + col] = o0;
            *(float2*)&C[(size_t)(mrow + 8) * G3 + col] = o1;
        }
    }
}

// ---------------- persistent GRU recurrence (tf32 mma.sync) ----------------
__device__ __forceinline__ float sigmoidf_(float x) { return 1.f / (1.f + __expf(-x)); }

#define HP 516  // hsm row stride: (516 % 32) == 4 -> A-frag banks (4r+c)%32 conflict-free

__global__ void __launch_bounds__(256, 1)
gru_kernel(const float* __restrict__ Whh,
           const float* __restrict__ bhh,
           int layer) {
    __shared__ float hsm[16 * HP];   // h[t] for our 16 batches (tf32-rounded)
    __shared__ float gsm[16 * 48];   // recurrent gate pre-activations
    __shared__ float bsm[48];

    const float* xp = g_xp;
    float* hout = layer ? g_h2 : g_h1;
    int* bar = g_bar[layer];

    const int tid = threadIdx.x;
    const int warp = tid >> 5;
    const int lane = tid & 31;
    const int bs = blockIdx.x & 3;
    const int js = blockIdx.x >> 2;
    const int b0 = bs * 16, j0 = js * 16;

    if (tid < 48) {
        int g = tid >> 4, j = tid & 15;
        bsm[tid] = bhh[g * 512 + j0 + j];
    }

    // ---- load W B-fragments into registers (warps 0-5 only) ----
    uint32_t wb0[64], wb1[64];
    const int r = lane >> 2, c = lane & 3;
    if (warp < 6) {
        int cg = warp * 8 + r;           // gate-col 0..47
        int g = cg >> 4, jj = cg & 15;
        const float* wrow = Whh + (size_t)(g * 512 + j0 + jj) * 512;
#pragma unroll
        for (int ks = 0; ks < 64; ks++) {
            wb0[ks] = cvt_tf32(wrow[ks * 8 + c]);
            wb1[ks] = cvt_tf32(wrow[ks * 8 + c + 4]);
        }
    }

    for (int idx = tid; idx < 16 * HP; idx += 256) hsm[idx] = 0.f;  // h0 = 0
    __syncthreads();

    const int gb = tid >> 4, gj = tid & 15;
    const float br = bsm[gj], bz = bsm[16 + gj], bn_ = bsm[32 + gj];
    float hprev = 0.f;

    const float* arow0 = hsm + r * HP;        // batch r
    const float* arow1 = hsm + (r + 8) * HP;  // batch r + 8

    for (int t = 0; t < TT; t++) {
        const float* xpt = xp + ((size_t)t * BB + b0 + gb) * G3 + j0 + gj;
        float xr = xpt[0], xz = xpt[512], xn = xpt[1024];

        if (warp < 6) {
            float acc0 = 0.f, acc1 = 0.f, acc2 = 0.f, acc3 = 0.f;
#pragma unroll
            for (int ks = 0; ks < 64; ks++) {
                int k = ks * 8;
                uint32_t a0 = __float_as_uint(arow0[k + c]);
                uint32_t a1 = __float_as_uint(arow1[k + c]);
                uint32_t a2 = __float_as_uint(arow0[k + c + 4]);
                uint32_t a3 = __float_as_uint(arow1[k + c + 4]);
                asm volatile(
                    "mma.sync.aligned.m16n8k8.row.col.f32.tf32.tf32.f32 "
                    "{%0,%1,%2,%3}, {%4,%5,%6,%7}, {%8,%9}, {%0,%1,%2,%3};\n"
                    : "+f"(acc0), "+f"(acc1), "+f"(acc2), "+f"(acc3)
                    : "r"(a0), "r"(a1), "r"(a2), "r"(a3),
                      "r"(wb0[ks]), "r"(wb1[ks]));
            }
            int cc = warp * 8 + 2 * c;
            gsm[r * 48 + cc]           = acc0;
            gsm[r * 48 + cc + 1]       = acc1;
            gsm[(r + 8) * 48 + cc]     = acc2;
            gsm[(r + 8) * 48 + cc + 1] = acc3;
        }
        __syncthreads();

        {
            float ar = gsm[gb * 48 + gj];
            float az = gsm[gb * 48 + 16 + gj];
            float an = gsm[gb * 48 + 32 + gj];
            float rr = sigmoidf_(xr + ar + br);
            float zz = sigmoidf_(xz + az + bz);
            float nn = tanhf(xn + rr * (an + bn_));
            float hnew = (1.f - zz) * nn + zz * hprev;
            hprev = hnew;
            hout[((size_t)t * BB + b0 + gb) * HH + j0 + gj] = hnew;
        }

        if (t == TT - 1) break;

        __threadfence();
        __syncthreads();
        if (tid == 0) {
            atomicAdd(&bar[t * 4 + bs], 1);
            volatile int* p = &bar[t * 4 + bs];
            while (*p < 32) { }
            __threadfence();
        }
        __syncthreads();

        for (int idx = tid; idx < 16 * 128; idx += 256) {
            int bb = idx >> 7, k4 = (idx & 127) * 4;
            float4 v = *(const float4*)(hout + ((size_t)t * BB + b0 + bb) * HH + k4);
            v.x = __uint_as_float(cvt_tf32(v.x));
            v.y = __uint_as_float(cvt_tf32(v.y));
            v.z = __uint_as_float(cvt_tf32(v.z));
            v.w = __uint_as_float(cvt_tf32(v.w));
            *(float4*)(hsm + bb * HP + k4) = v;
        }
        __syncthreads();
    }
}

// ---------------- mean pool over batch + FC ----------------
__global__ void pool_fc_kernel(const float* __restrict__ fcW,
                               const float* __restrict__ fcb,
                               float* __restrict__ out) {
    __shared__ float pooled[HH];
    int t = blockIdx.x;
    const float* base = g_h2 + (size_t)t * BB * HH;
    for (int h = threadIdx.x; h < HH; h += blockDim.x) {
        float s = 0.f;
        for (int b = 0; b < BB; b++) s += base[b * HH + h];
        pooled[h] = s * (1.f / 64.f);
    }
    __syncthreads();
    int w = threadIdx.x >> 5, lane = threadIdx.x & 31;
    if (w < LL) {
        float s = 0.f;
        for (int h = lane; h < HH; h += 32) s = fmaf(pooled[h], fcW[w * HH + h], s);
#pragma unroll
        for (int o = 16; o > 0; o >>= 1) s += __shfl_xor_sync(0xffffffffu, s, o);
        if (lane == 0) out[t * LL + w] = s + fcb[w];
    }
}

// ---------------- launch ----------------
extern "C" void kernel_launch(void* const* d_in, const int* in_sizes, int n_in,
                              void* d_out, int out_size) {
    (void)in_sizes; (void)n_in; (void)out_size;
    const int*   texts = (const int*)d_in[0];
    const float* emb   = (const float*)d_in[1];
    const float* Wih0  = (const float*)d_in[2];
    const float* Whh0  = (const float*)d_in[3];
    const float* bih0  = (const float*)d_in[4];
    const float* bhh0  = (const float*)d_in[5];
    const float* Wih1  = (const float*)d_in[6];
    const float* Whh1  = (const float*)d_in[7];
    const float* bih1  = (const float*)d_in[8];
    const float* bhh1  = (const float*)d_in[9];
    const float* fcW   = (const float*)d_in[10];
    const float* fcb   = (const float*)d_in[11];
    float* out = (float*)d_out;

    zero_bar_kernel<<<16, 256>>>();
    embed_kernel<<<TB, 128>>>(texts, emb);

    dim3 ggrid(TB / 128, G3 / 128);
    gemm_tf32_kernel<<<ggrid, 256>>>(Wih0, bih0, EE, 0);   // xp0 from g_x
    gru_kernel<<<128, 256>>>(Whh0, bhh0, 0);               // -> g_h1
    gemm_tf32_kernel<<<ggrid, 256>>>(Wih1, bih1, HH, 1);   // xp1 from g_h1
    gru_kernel<<<128, 256>>>(Whh1, bhh1, 1);               // -> g_h2
    pool_fc_kernel<<<TT, 256>>>(fcW, fcb, out);
}

// round 6
// speedup vs baseline: 2.9478x; 1.1195x over previous
#include <cuda_runtime.h>
#include <math.h>
#include <stdint.h>

#define TT 512
#define BB 64
#define EE 300
#define HH 512
#define LL 5
#define TB (TT*BB)
#define G3 (3*HH)

// ---------------- scratch (static device globals; no allocation) ----------------
__device__ float g_x[TB * EE];     // embedded inputs [T*B, 300]
__device__ float g_xp[TB * G3];    // input projections for current layer [T*B, 1536]
__device__ float g_h1[TB * HH];    // layer-0 hidden outputs [T*B, 512]
__device__ float g_h2[TB * HH];    // layer-1 hidden outputs [T*B, 512]
__device__ int   g_bar[2][TT * 4]; // per (layer, step, batch-group) barrier counters

__device__ __forceinline__ uint32_t cvt_tf32(float f) {
    uint32_t u;
    asm("cvt.rna.tf32.f32 %0, %1;" : "=r"(u) : "f"(f));
    return u;
}

// ---------------- barrier reset ----------------
__global__ void zero_bar_kernel() {
    int i = blockIdx.x * blockDim.x + threadIdx.x;
    if (i < 2 * TT * 4) ((int*)g_bar)[i] = 0;
}

// ---------------- embedding gather ----------------
__global__ void embed_kernel(const int* __restrict__ texts,
                             const float* __restrict__ emb) {
    int row = blockIdx.x;                       // t*B + b
    int v = texts[row];
    const float* src = emb + (size_t)v * EE;
    float* dst = g_x + (size_t)row * EE;
    for (int e = threadIdx.x; e < EE; e += blockDim.x) dst[e] = src[e];
}

// ---------------- C[M,1536] = A[M,K] @ W[1536,K]^T + bias  (tf32 mma) ----------------
// BM=128, BN=128, BK=16, 256 threads, 8 warps as 4(M) x 2(N), warp tile 32x64.
__global__ void __launch_bounds__(256)
gemm_tf32_kernel(const float* __restrict__ W,
                 const float* __restrict__ bias,
                 int K, int useA1) {
    __shared__ float As[16][136];   // [k][m], stride 136 -> conflict-free frag loads
    __shared__ float Bs[16][136];   // [k][n]
    const float* A = useA1 ? g_h1 : g_x;
    float* C = g_xp;
    const int tid = threadIdx.x;
    const int bm = blockIdx.x * 128;
    const int bn = blockIdx.y * 128;
    const int warp = tid >> 5, lane = tid & 31;
    const int wm = warp >> 1, wn = warp & 1;
    const int m0 = wm * 32, n0 = wn * 64;
    const int r = lane >> 2, c = lane & 3;

    float acc[2][8][4];
#pragma unroll
    for (int mt = 0; mt < 2; mt++)
#pragma unroll
        for (int nt = 0; nt < 8; nt++)
#pragma unroll
            for (int q = 0; q < 4; q++) acc[mt][nt][q] = 0.f;

    const int lrow = tid & 127;
    const int lk = (tid >> 7) * 8;

    for (int k0 = 0; k0 < K; k0 += 16) {
        {   // A tile
            const float* ap = A + (size_t)(bm + lrow) * K + k0 + lk;
            float v[8];
            if (k0 + lk + 7 < K) {
                float4 p = *(const float4*)ap;
                float4 q4 = *(const float4*)(ap + 4);
                v[0]=p.x; v[1]=p.y; v[2]=p.z; v[3]=p.w;
                v[4]=q4.x; v[5]=q4.y; v[6]=q4.z; v[7]=q4.w;
            } else {
#pragma unroll
                for (int q = 0; q < 8; q++) {
                    int k = k0 + lk + q;
                    v[q] = (k < K) ? ap[q] : 0.f;
                }
            }
#pragma unroll
            for (int q = 0; q < 8; q++)
                As[lk + q][lrow] = __uint_as_float(cvt_tf32(v[q]));
        }
        {   // B tile
            const float* wp = W + (size_t)(bn + lrow) * K + k0 + lk;
            float v[8];
            if (k0 + lk + 7 < K) {
                float4 p = *(const float4*)wp;
                float4 q4 = *(const float4*)(wp + 4);
                v[0]=p.x; v[1]=p.y; v[2]=p.z; v[3]=p.w;
                v[4]=q4.x; v[5]=q4.y; v[6]=q4.z; v[7]=q4.w;
            } else {
#pragma unroll
                for (int q = 0; q < 8; q++) {
                    int k = k0 + lk + q;
                    v[q] = (k < K) ? wp[q] : 0.f;
                }
            }
#pragma unroll
            for (int q = 0; q < 8; q++)
                Bs[lk + q][lrow] = __uint_as_float(cvt_tf32(v[q]));
        }
        __syncthreads();
#pragma unroll
        for (int ks = 0; ks < 16; ks += 8) {
            uint32_t af[2][4], bf[8][2];
#pragma unroll
            for (int mt = 0; mt < 2; mt++) {
                int mm = m0 + mt * 16;
                af[mt][0] = __float_as_uint(As[ks + c][mm + r]);
                af[mt][1] = __float_as_uint(As[ks + c][mm + r + 8]);
                af[mt][2] = __float_as_uint(As[ks + c + 4][mm + r]);
                af[mt][3] = __float_as_uint(As[ks + c + 4][mm + r + 8]);
            }
#pragma unroll
            for (int nt = 0; nt < 8; nt++) {
                int nn = n0 + nt * 8 + r;
                bf[nt][0] = __float_as_uint(Bs[ks + c][nn]);
                bf[nt][1] = __float_as_uint(Bs[ks + c + 4][nn]);
            }
#pragma unroll
            for (int mt = 0; mt < 2; mt++)
#pragma unroll
                for (int nt = 0; nt < 8; nt++) {
                    asm volatile(
                        "mma.sync.aligned.m16n8k8.row.col.f32.tf32.tf32.f32 "
                        "{%0,%1,%2,%3}, {%4,%5,%6,%7}, {%8,%9}, {%0,%1,%2,%3};\n"
                        : "+f"(acc[mt][nt][0]), "+f"(acc[mt][nt][1]),
                          "+f"(acc[mt][nt][2]), "+f"(acc[mt][nt][3])
                        : "r"(af[mt][0]), "r"(af[mt][1]), "r"(af[mt][2]), "r"(af[mt][3]),
                          "r"(bf[nt][0]), "r"(bf[nt][1]));
                }
        }
        __syncthreads();
    }
#pragma unroll
    for (int mt = 0; mt < 2; mt++) {
        int mrow = bm + m0 + mt * 16 + r;
#pragma unroll
        for (int nt = 0; nt < 8; nt++) {
            int col = bn + n0 + nt * 8 + 2 * c;
            float b0 = bias[col], b1 = bias[col + 1];
            float2 o0, o1;
            o0.x = acc[mt][nt][0] + b0; o0.y = acc[mt][nt][1] + b1;
            o1.x = acc[mt][nt][2] + b0; o1.y = acc[mt][nt][3] + b1;
            *(float2*)&C[(size_t)mrow * G3 + col] = o0;
            *(float2*)&C[(size_t)(mrow + 8) * G3 + col] = o1;
        }
    }
}

// ---------------- persistent GRU recurrence (tf32 mma.sync) ----------------
__device__ __forceinline__ float sigmoidf_(float x) { return 1.f / (1.f + __expf(-x)); }

#define HP 516  // hsm row stride: (516 % 32) == 4 -> A-frag banks (4r+c)%32 conflict-free

__global__ void __launch_bounds__(256, 1)
gru_kernel(const float* __restrict__ Whh,
           const float* __restrict__ bhh,
           int layer) {
    __shared__ float hsm[16 * HP];   // h[t] for our 16 batches (tf32-rounded)
    __shared__ float gsm[16 * 48];   // recurrent gate pre-activations
    __shared__ float bsm[48];

    const float* xp = g_xp;
    float* hout = layer ? g_h2 : g_h1;
    int* bar = g_bar[layer];

    const int tid = threadIdx.x;
    const int warp = tid >> 5;
    const int lane = tid & 31;
    const int bs = blockIdx.x & 3;
    const int js = blockIdx.x >> 2;
    const int b0 = bs * 16, j0 = js * 16;

    if (tid < 48) {
        int g = tid >> 4, j = tid & 15;
        bsm[tid] = bhh[g * 512 + j0 + j];
    }

    // ---- load W B-fragments into registers (warps 0-5 only) ----
    uint32_t wb0[64], wb1[64];
    const int r = lane >> 2, c = lane & 3;
    if (warp < 6) {
        int cg = warp * 8 + r;           // gate-col 0..47
        int g = cg >> 4, jj = cg & 15;
        const float* wrow = Whh + (size_t)(g * 512 + j0 + jj) * 512;
#pragma unroll
        for (int ks = 0; ks < 64; ks++) {
            wb0[ks] = cvt_tf32(wrow[ks * 8 + c]);
            wb1[ks] = cvt_tf32(wrow[ks * 8 + c + 4]);
        }
    }

    for (int idx = tid; idx < 16 * HP; idx += 256) hsm[idx] = 0.f;  // h0 = 0
    __syncthreads();

    const int gb = tid >> 4, gj = tid & 15;
    const float br = bsm[gj], bz = bsm[16 + gj], bn_ = bsm[32 + gj];
    float hprev = 0.f;

    const float* arow0 = hsm + r * HP;        // batch r
    const float* arow1 = hsm + (r + 8) * HP;  // batch r + 8

    for (int t = 0; t < TT; t++) {
        const float* xpt = xp + ((size_t)t * BB + b0 + gb) * G3 + j0 + gj;
        float xr = xpt[0], xz = xpt[512], xn = xpt[1024];

        if (warp < 6) {
            // 4 independent accumulator groups -> mma dependency chain 64 -> 16
            float ac[4][4];
#pragma unroll
            for (int g4 = 0; g4 < 4; g4++)
#pragma unroll
                for (int q = 0; q < 4; q++) ac[g4][q] = 0.f;
#pragma unroll
            for (int ks = 0; ks < 64; ks += 4) {
#pragma unroll
                for (int g4 = 0; g4 < 4; g4++) {
                    int k = (ks + g4) * 8;
                    uint32_t a0 = __float_as_uint(arow0[k + c]);
                    uint32_t a1 = __float_as_uint(arow1[k + c]);
                    uint32_t a2 = __float_as_uint(arow0[k + c + 4]);
                    uint32_t a3 = __float_as_uint(arow1[k + c + 4]);
                    asm volatile(
                        "mma.sync.aligned.m16n8k8.row.col.f32.tf32.tf32.f32 "
                        "{%0,%1,%2,%3}, {%4,%5,%6,%7}, {%8,%9}, {%0,%1,%2,%3};\n"
                        : "+f"(ac[g4][0]), "+f"(ac[g4][1]),
                          "+f"(ac[g4][2]), "+f"(ac[g4][3])
                        : "r"(a0), "r"(a1), "r"(a2), "r"(a3),
                          "r"(wb0[ks + g4]), "r"(wb1[ks + g4]));
                }
            }
            float acc0 = (ac[0][0] + ac[1][0]) + (ac[2][0] + ac[3][0]);
            float acc1 = (ac[0][1] + ac[1][1]) + (ac[2][1] + ac[3][1]);
            float acc2 = (ac[0][2] + ac[1][2]) + (ac[2][2] + ac[3][2]);
            float acc3 = (ac[0][3] + ac[1][3]) + (ac[2][3] + ac[3][3]);
            int cc = warp * 8 + 2 * c;
            gsm[r * 48 + cc]           = acc0;
            gsm[r * 48 + cc + 1]       = acc1;
            gsm[(r + 8) * 48 + cc]     = acc2;
            gsm[(r + 8) * 48 + cc + 1] = acc3;
        }
        __syncthreads();

        {
            float ar = gsm[gb * 48 + gj];
            float az = gsm[gb * 48 + 16 + gj];
            float an = gsm[gb * 48 + 32 + gj];
            float rr = sigmoidf_(xr + ar + br);
            float zz = sigmoidf_(xz + az + bz);
            float nn = tanhf(xn + rr * (an + bn_));
            float hnew = (1.f - zz) * nn + zz * hprev;
            hprev = hnew;
            hout[((size_t)t * BB + b0 + gb) * HH + j0 + gj] = hnew;
        }

        if (t == TT - 1) break;

        // ---- release/acquire group barrier (32 CTAs sharing this batch-group) ----
        __syncthreads();                 // all STGs of hnew done CTA-wide
        if (tid == 0) {
            int* flag = &bar[t * 4 + bs];
            asm volatile("red.release.gpu.global.add.s32 [%0], 1;" :: "l"(flag) : "memory");
            int v;
            do {
                asm volatile("ld.acquire.gpu.global.s32 %0, [%1];" : "=r"(v) : "l"(flag) : "memory");
            } while (v < 32);
        }
        __syncthreads();

        // ---- reload full h[t] for our 16 batches, batched for MLP ----
        {
            const float* src = hout + ((size_t)t * BB + b0) * HH;
            float4 vv[8];
#pragma unroll
            for (int q = 0; q < 8; q++) {
                int idx = tid + q * 256;          // 0..2047
                int bb = idx >> 7, k4 = (idx & 127) * 4;
                vv[q] = *(const float4*)(src + (size_t)bb * HH + k4);
            }
#pragma unroll
            for (int q = 0; q < 8; q++) {
                int idx = tid + q * 256;
                int bb = idx >> 7, k4 = (idx & 127) * 4;
                float4 v = vv[q];
                v.x = __uint_as_float(cvt_tf32(v.x));
                v.y = __uint_as_float(cvt_tf32(v.y));
                v.z = __uint_as_float(cvt_tf32(v.z));
                v.w = __uint_as_float(cvt_tf32(v.w));
                *(float4*)(hsm + bb * HP + k4) = v;
            }
        }
        __syncthreads();
    }
}

// ---------------- mean pool over batch + FC ----------------
__global__ void pool_fc_kernel(const float* __restrict__ fcW,
                               const float* __restrict__ fcb,
                               float* __restrict__ out) {
    __shared__ float pooled[HH];
    int t = blockIdx.x;
    const float* base = g_h2 + (size_t)t * BB * HH;
    for (int h = threadIdx.x; h < HH; h += blockDim.x) {
        float s = 0.f;
        for (int b = 0; b < BB; b++) s += base[b * HH + h];
        pooled[h] = s * (1.f / 64.f);
    }
    __syncthreads();
    int w = threadIdx.x >> 5, lane = threadIdx.x & 31;
    if (w < LL) {
        float s = 0.f;
        for (int h = lane; h < HH; h += 32) s = fmaf(pooled[h], fcW[w * HH + h], s);
#pragma unroll
        for (int o = 16; o > 0; o >>= 1) s += __shfl_xor_sync(0xffffffffu, s, o);
        if (lane == 0) out[t * LL + w] = s + fcb[w];
    }
}

// ---------------- launch ----------------
extern "C" void kernel_launch(void* const* d_in, const int* in_sizes, int n_in,
                              void* d_out, int out_size) {
    (void)in_sizes; (void)n_in; (void)out_size;
    const int*   texts = (const int*)d_in[0];
    const float* emb   = (const float*)d_in[1];
    const float* Wih0  = (const float*)d_in[2];
    const float* Whh0  = (const float*)d_in[3];
    const float* bih0  = (const float*)d_in[4];
    const float* bhh0  = (const float*)d_in[5];
    const float* Wih1  = (const float*)d_in[6];
    const float* Whh1  = (const float*)d_in[7];
    const float* bih1  = (const float*)d_in[8];
    const float* bhh1  = (const float*)d_in[9];
    const float* fcW   = (const float*)d_in[10];
    const float* fcb   = (const float*)d_in[11];
    float* out = (float*)d_out;

    zero_bar_kernel<<<16, 256>>>();
    embed_kernel<<<TB, 128>>>(texts, emb);

    dim3 ggrid(TB / 128, G3 / 128);
    gemm_tf32_kernel<<<ggrid, 256>>>(Wih0, bih0, EE, 0);   // xp0 from g_x
    gru_kernel<<<128, 256>>>(Whh0, bhh0, 0);               // -> g_h1
    gemm_tf32_kernel<<<ggrid, 256>>>(Wih1, bih1, HH, 1);   // xp1 from g_h1
    gru_kernel<<<128, 256>>>(Whh1, bhh1, 1);               // -> g_h2
    pool_fc_kernel<<<TT, 256>>>(fcW, fcb, out);
}

// round 8
// speedup vs baseline: 3.4328x; 1.1645x over previous
#include <cuda_runtime.h>
#include <cuda_fp16.h>
#include <math.h>
#include <stdint.h>

#define TT 512
#define BB 64
#define EE 300
#define HH 512
#define LL 5
#define TB (TT*BB)
#define G3 (3*HH)

// ---------------- scratch (static device globals; no allocation) ----------------
__device__ float  g_x[TB * EE];     // embedded inputs [T*B, 300]
__device__ float  g_xp[TB * G3];    // input projections for current layer [T*B, 1536]
__device__ float  g_h1[TB * HH];    // layer-0 hidden outputs [T*B, 512] (fp32, feeds gemm1)
__device__ float  g_h2[TB * HH];    // layer-1 hidden outputs [T*B, 512] (fp32, feeds pool)
__device__ __half g_hex[TB * HH];   // fp16 h exchange buffer (per-step slots)
__device__ int    g_bar[2][TT * 4]; // per (layer, step, batch-group) barrier counters

__device__ __forceinline__ uint32_t cvt_tf32(float f) {
    uint32_t u;
    asm("cvt.rna.tf32.f32 %0, %1;" : "=r"(u) : "f"(f));
    return u;
}

// pack two fp32 -> fp16x2 in a uint32 (lo = a, hi = b)
__device__ __forceinline__ uint32_t pack_f16x2(float a, float b) {
    uint32_t u;
    asm("cvt.rn.f16x2.f32 %0, %2, %1;" : "=r"(u) : "f"(a), "f"(b));
    return u;
}

// ---------------- barrier reset ----------------
__global__ void zero_bar_kernel() {
    int i = blockIdx.x * blockDim.x + threadIdx.x;
    if (i < 2 * TT * 4) ((int*)g_bar)[i] = 0;
}

// ---------------- embedding gather ----------------
__global__ void embed_kernel(const int* __restrict__ texts,
                             const float* __restrict__ emb) {
    int row = blockIdx.x;                       // t*B + b
    int v = texts[row];
    const float* src = emb + (size_t)v * EE;
    float* dst = g_x + (size_t)row * EE;
    for (int e = threadIdx.x; e < EE; e += blockDim.x) dst[e] = src[e];
}

// ---------------- C[M,1536] = A[M,K] @ W[1536,K]^T + bias  (tf32 mma) ----------------
__global__ void __launch_bounds__(256)
gemm_tf32_kernel(const float* __restrict__ W,
                 const float* __restrict__ bias,
                 int K, int useA1) {
    __shared__ float As[16][136];
    __shared__ float Bs[16][136];
    const float* A = useA1 ? g_h1 : g_x;
    float* C = g_xp;
    const int tid = threadIdx.x;
    const int bm = blockIdx.x * 128;
    const int bn = blockIdx.y * 128;
    const int warp = tid >> 5, lane = tid & 31;
    const int wm = warp >> 1, wn = warp & 1;
    const int m0 = wm * 32, n0 = wn * 64;
    const int r = lane >> 2, c = lane & 3;

    float acc[2][8][4];
#pragma unroll
    for (int mt = 0; mt < 2; mt++)
#pragma unroll
        for (int nt = 0; nt < 8; nt++)
#pragma unroll
            for (int q = 0; q < 4; q++) acc[mt][nt][q] = 0.f;

    const int lrow = tid & 127;
    const int lk = (tid >> 7) * 8;

    for (int k0 = 0; k0 < K; k0 += 16) {
        {
            const float* ap = A + (size_t)(bm + lrow) * K + k0 + lk;
            float v[8];
            if (k0 + lk + 7 < K) {
                float4 p = *(const float4*)ap;
                float4 q4 = *(const float4*)(ap + 4);
                v[0]=p.x; v[1]=p.y; v[2]=p.z; v[3]=p.w;
                v[4]=q4.x; v[5]=q4.y; v[6]=q4.z; v[7]=q4.w;
            } else {
#pragma unroll
                for (int q = 0; q < 8; q++) {
                    int k = k0 + lk + q;
                    v[q] = (k < K) ? ap[q] : 0.f;
                }
            }
#pragma unroll
            for (int q = 0; q < 8; q++)
                As[lk + q][lrow] = __uint_as_float(cvt_tf32(v[q]));
        }
        {
            const float* wp = W + (size_t)(bn + lrow) * K + k0 + lk;
            float v[8];
            if (k0 + lk + 7 < K) {
                float4 p = *(const float4*)wp;
                float4 q4 = *(const float4*)(wp + 4);
                v[0]=p.x; v[1]=p.y; v[2]=p.z; v[3]=p.w;
                v[4]=q4.x; v[5]=q4.y; v[6]=q4.z; v[7]=q4.w;
            } else {
#pragma unroll
                for (int q = 0; q < 8; q++) {
                    int k = k0 + lk + q;
                    v[q] = (k < K) ? wp[q] : 0.f;
                }
            }
#pragma unroll
            for (int q = 0; q < 8; q++)
                Bs[lk + q][lrow] = __uint_as_float(cvt_tf32(v[q]));
        }
        __syncthreads();
#pragma unroll
        for (int ks = 0; ks < 16; ks += 8) {
            uint32_t af[2][4], bf[8][2];
#pragma unroll
            for (int mt = 0; mt < 2; mt++) {
                int mm = m0 + mt * 16;
                af[mt][0] = __float_as_uint(As[ks + c][mm + r]);
                af[mt][1] = __float_as_uint(As[ks + c][mm + r + 8]);
                af[mt][2] = __float_as_uint(As[ks + c + 4][mm + r]);
                af[mt][3] = __float_as_uint(As[ks + c + 4][mm + r + 8]);
            }
#pragma unroll
            for (int nt = 0; nt < 8; nt++) {
                int nn = n0 + nt * 8 + r;
                bf[nt][0] = __float_as_uint(Bs[ks + c][nn]);
                bf[nt][1] = __float_as_uint(Bs[ks + c + 4][nn]);
            }
#pragma unroll
            for (int mt = 0; mt < 2; mt++)
#pragma unroll
                for (int nt = 0; nt < 8; nt++) {
                    asm volatile(
                        "mma.sync.aligned.m16n8k8.row.col.f32.tf32.tf32.f32 "
                        "{%0,%1,%2,%3}, {%4,%5,%6,%7}, {%8,%9}, {%0,%1,%2,%3};\n"
                        : "+f"(acc[mt][nt][0]), "+f"(acc[mt][nt][1]),
                          "+f"(acc[mt][nt][2]), "+f"(acc[mt][nt][3])
                        : "r"(af[mt][0]), "r"(af[mt][1]), "r"(af[mt][2]), "r"(af[mt][3]),
                          "r"(bf[nt][0]), "r"(bf[nt][1]));
                }
        }
        __syncthreads();
    }
#pragma unroll
    for (int mt = 0; mt < 2; mt++) {
        int mrow = bm + m0 + mt * 16 + r;
#pragma unroll
        for (int nt = 0; nt < 8; nt++) {
            int col = bn + n0 + nt * 8 + 2 * c;
            float b0 = bias[col], b1 = bias[col + 1];
            float2 o0, o1;
            o0.x = acc[mt][nt][0] + b0; o0.y = acc[mt][nt][1] + b1;
            o1.x = acc[mt][nt][2] + b0; o1.y = acc[mt][nt][3] + b1;
            *(float2*)&C[(size_t)mrow * G3 + col] = o0;
            *(float2*)&C[(size_t)(mrow + 8) * G3 + col] = o1;
        }
    }
}

// ---------------- persistent GRU recurrence (fp16 mma, W as A-operand) ----------------
__device__ __forceinline__ float sigmoidf_(float x) { return 1.f / (1.f + __expf(-x)); }

#define HEP 520   // hsm (fp16) row stride in halves: 1040B -> +4 banks/row, conflict-free
#define GSP 52    // gsm row stride in floats: conflict-free C-frag stores

__global__ void __launch_bounds__(256, 1)
gru_kernel(const float* __restrict__ Whh,
           const float* __restrict__ bhh,
           int layer) {
    __shared__ __half hsm[16 * HEP];   // h[t] for our 16 batches, fp16
    __shared__ float  gsm[16 * GSP];   // recurrent gate pre-activations [batch][gateCol]
    __shared__ float  bsm[48];

    const float* xp = g_xp;
    float* hout = layer ? g_h2 : g_h1;
    int* bar = g_bar[layer];

    const int tid = threadIdx.x;
    const int warp = tid >> 5;
    const int lane = tid & 31;
    const int bs = blockIdx.x & 3;
    const int js = blockIdx.x >> 2;
    const int b0 = bs * 16, j0 = js * 16;

    if (tid < 48) {
        int g = tid >> 4, j = tid & 15;
        bsm[tid] = bhh[g * 512 + j0 + j];
    }

    // ---- load W A-fragments into fp16x2 registers (warps 0-5) ----
    // warp = mtile*2 + wn; mtile = gate type (0=r,1=z,2=n); wn = batch n-tile
    const int r = lane >> 2, c = lane & 3;
    const int mtile = warp >> 1, wn = warp & 1;
    uint32_t wa0[32], wa1[32], wa2[32], wa3[32];
    if (warp < 6) {
        const float* rowa = Whh + (size_t)(mtile * 512 + j0 + r) * 512;
        const float* rowb = Whh + (size_t)(mtile * 512 + j0 + r + 8) * 512;
#pragma unroll
        for (int ks = 0; ks < 32; ks++) {
            int k = ks * 16 + 2 * c;
            float2 p0 = *(const float2*)(rowa + k);
            float2 p1 = *(const float2*)(rowb + k);
            float2 p2 = *(const float2*)(rowa + k + 8);
            float2 p3 = *(const float2*)(rowb + k + 8);
            wa0[ks] = pack_f16x2(p0.x, p0.y);
            wa1[ks] = pack_f16x2(p1.x, p1.y);
            wa2[ks] = pack_f16x2(p2.x, p2.y);
            wa3[ks] = pack_f16x2(p3.x, p3.y);
        }
    }

    for (int idx = tid; idx < 16 * HEP / 2; idx += 256)
        ((uint32_t*)hsm)[idx] = 0u;     // h0 = 0
    __syncthreads();

    const int gb = tid >> 4, gj = tid & 15;
    const float br = bsm[gj], bz = bsm[16 + gj], bn_ = bsm[32 + gj];
    float hprev = 0.f;

    // B-frag source rows: batch = wn*8 + r
    const __half* hrow = hsm + (wn * 8 + r) * HEP;

    for (int t = 0; t < TT; t++) {
        const float* xpt = xp + ((size_t)t * BB + b0 + gb) * G3 + j0 + gj;
        float xr = xpt[0], xz = xpt[512], xn = xpt[1024];

        if (warp < 6) {
            // 4 independent accumulator groups -> 8-deep mma chains
            float ac[4][4];
#pragma unroll
            for (int g4 = 0; g4 < 4; g4++)
#pragma unroll
                for (int q = 0; q < 4; q++) ac[g4][q] = 0.f;
#pragma unroll
            for (int ks = 0; ks < 32; ks += 4) {
#pragma unroll
                for (int g4 = 0; g4 < 4; g4++) {
                    int k = (ks + g4) * 16 + 2 * c;
                    uint32_t bfr0 = *(const uint32_t*)(hrow + k);
                    uint32_t bfr1 = *(const uint32_t*)(hrow + k + 8);
                    asm volatile(
                        "mma.sync.aligned.m16n8k16.row.col.f32.f16.f16.f32 "
                        "{%0,%1,%2,%3}, {%4,%5,%6,%7}, {%8,%9}, {%0,%1,%2,%3};\n"
                        : "+f"(ac[g4][0]), "+f"(ac[g4][1]),
                          "+f"(ac[g4][2]), "+f"(ac[g4][3])
                        : "r"(wa0[ks + g4]), "r"(wa1[ks + g4]),
                          "r"(wa2[ks + g4]), "r"(wa3[ks + g4]),
                          "r"(bfr0), "r"(bfr1));
                }
            }
            float d0 = (ac[0][0] + ac[1][0]) + (ac[2][0] + ac[3][0]);
            float d1 = (ac[0][1] + ac[1][1]) + (ac[2][1] + ac[3][1]);
            float d2 = (ac[0][2] + ac[1][2]) + (ac[2][2] + ac[3][2]);
            float d3 = (ac[0][3] + ac[1][3]) + (ac[2][3] + ac[3][3]);
            // D[gate row, batch col]: d0=(r,2c) d1=(r,2c+1) d2=(r+8,2c) d3=(r+8,2c+1)
            int bb0 = wn * 8 + 2 * c;
            int gc0 = mtile * 16 + r;
            gsm[bb0 * GSP + gc0]           = d0;
            gsm[(bb0 + 1) * GSP + gc0]     = d1;
            gsm[bb0 * GSP + gc0 + 8]       = d2;
            gsm[(bb0 + 1) * GSP + gc0 + 8] = d3;
        }
        __syncthreads();

        {
            float ar = gsm[gb * GSP + gj];
            float az = gsm[gb * GSP + 16 + gj];
            float an = gsm[gb * GSP + 32 + gj];
            float rr = sigmoidf_(xr + ar + br);
            float zz = sigmoidf_(xz + az + bz);
            float nn = tanhf(xn + rr * (an + bn_));
            float hnew = (1.f - zz) * nn + zz * hprev;
            hprev = hnew;
            size_t orow = (size_t)t * BB + b0 + gb;
            hout[orow * HH + j0 + gj] = hnew;                       // fp32 (downstream)
            g_hex[orow * HH + j0 + gj] = __float2half_rn(hnew);     // fp16 (exchange)
        }

        if (t == TT - 1) break;

        // ---- release/acquire group barrier (32 CTAs sharing this batch-group) ----
        __syncthreads();
        if (tid == 0) {
            int* flag = &bar[t * 4 + bs];
            asm volatile("red.release.gpu.global.add.s32 [%0], 1;" :: "l"(flag) : "memory");
            int v;
            do {
                asm volatile("ld.acquire.gpu.global.s32 %0, [%1];" : "=r"(v) : "l"(flag) : "memory");
            } while (v < 32);
        }
        __syncthreads();

        // ---- reload full fp16 h[t] for our 16 batches (16 KB), batched for MLP ----
        {
            const __half* src = g_hex + ((size_t)t * BB + b0) * HH;
            uint4 vv[4];
#pragma unroll
            for (int q = 0; q < 4; q++) {
                int idx = tid + q * 256;          // 0..1023 chunks of 8 halves
                int bb = idx >> 6, ch = idx & 63;
                vv[q] = *(const uint4*)(src + (size_t)bb * HH + ch * 8);
            }
#pragma unroll
            for (int q = 0; q < 4; q++) {
                int idx = tid + q * 256;
                int bb = idx >> 6, ch = idx & 63;
                *(uint4*)(hsm + bb * HEP + ch * 8) = vv[q];
            }
        }
        __syncthreads();
    }
}

// ---------------- mean pool over batch + FC ----------------
__global__ void pool_fc_kernel(const float* __restrict__ fcW,
                               const float* __restrict__ fcb,
                               float* __restrict__ out) {
    __shared__ float pooled[HH];
    int t = blockIdx.x;
    const float* base = g_h2 + (size_t)t * BB * HH;
    for (int h = threadIdx.x; h < HH; h += blockDim.x) {
        float s = 0.f;
        for (int b = 0; b < BB; b++) s += base[b * HH + h];
        pooled[h] = s * (1.f / 64.f);
    }
    __syncthreads();
    int w = threadIdx.x >> 5, lane = threadIdx.x & 31;
    if (w < LL) {
        float s = 0.f;
        for (int h = lane; h < HH; h += 32) s = fmaf(pooled[h], fcW[w * HH + h], s);
#pragma unroll
        for (int o = 16; o > 0; o >>= 1) s += __shfl_xor_sync(0xffffffffu, s, o);
        if (lane == 0) out[t * LL + w] = s + fcb[w];
    }
}

// ---------------- launch ----------------
extern "C" void kernel_launch(void* const* d_in, const int* in_sizes, int n_in,
                              void* d_out, int out_size) {
    (void)in_sizes; (void)n_in; (void)out_size;
    const int*   texts = (const int*)d_in[0];
    const float* emb   = (const float*)d_in[1];
    const float* Wih0  = (const float*)d_in[2];
    const float* Whh0  = (const float*)d_in[3];
    const float* bih0  = (const float*)d_in[4];
    const float* bhh0  = (const float*)d_in[5];
    const float* Wih1  = (const float*)d_in[6];
    const float* Whh1  = (const float*)d_in[7];
    const float* bih1  = (const float*)d_in[8];
    const float* bhh1  = (const float*)d_in[9];
    const float* fcW   = (const float*)d_in[10];
    const float* fcb   = (const float*)d_in[11];
    float* out = (float*)d_out;

    zero_bar_kernel<<<16, 256>>>();
    embed_kernel<<<TB, 128>>>(texts, emb);

    dim3 ggrid(TB / 128, G3 / 128);
    gemm_tf32_kernel<<<ggrid, 256>>>(Wih0, bih0, EE, 0);   // xp0 from g_x
    gru_kernel<<<128, 256>>>(Whh0, bhh0, 0);               // -> g_h1
    gemm_tf32_kernel<<<ggrid, 256>>>(Wih1, bih1, HH, 1);   // xp1 from g_h1
    gru_kernel<<<128, 256>>>(Whh1, bhh1, 1);               // -> g_h2
    pool_fc_kernel<<<TT, 256>>>(fcW, fcb, out);
}